// round 15
// baseline (speedup 1.0000x reference)
#include <cuda_runtime.h>
#include <math.h>

#define BB    16
#define TT    3300
#define FEAT  80
#define NC    512
#define RNN   512
#define G3    1536
#define DIN   592
#define NBLK  128   // persistent GRU blocks (256 threads each)

// ---------------- device scratch (no allocation allowed) ----------------
__device__ float    g_melsup[(size_t)BB * TT * FEAT];     // [b][t][f]
__device__ float    g_wohT[(size_t)NC * G3];              // [class][gate-row]
__device__ float    g_xproj[(size_t)TT * G3 * BB];        // [t][row][b] (includes b_ih)
__device__ float    g_hs[(size_t)BB * TT * RNN];          // GRU outputs
__device__ float    g_h1[(size_t)BB * TT * RNN];          // fc1 output
__device__ float    g_hbuf[2][BB * RNN];                  // ping-pong hidden state
__device__ unsigned g_flag[NBLK];                         // per-block step flags

__device__ __forceinline__ float sigm(float x) { return 1.f / (1.f + __expf(-x)); }
__device__ __forceinline__ float ftanh(float x) {
    x = fminf(fmaxf(x, -15.f), 15.f);
    float e = __expf(-2.f * x);
    return __fdividef(1.f - e, 1.f + e);
}

// tf32 hi/lo split + m16n8k8 MMA
__device__ __forceinline__ void split_tf32(float v, unsigned &hi, unsigned &lo) {
    unsigned h;
    asm("cvt.rna.tf32.f32 %0, %1;" : "=r"(h) : "f"(v));
    float l = v - __uint_as_float(h);
    asm("cvt.rna.tf32.f32 %0, %1;" : "=r"(lo) : "f"(l));
    hi = h;
}

#define MMA_TF32(c, a, b) \
    asm volatile("mma.sync.aligned.m16n8k8.row.col.f32.tf32.tf32.f32 " \
        "{%0,%1,%2,%3}, {%4,%5,%6,%7}, {%8,%9}, {%0,%1,%2,%3};" \
        : "+f"(c[0]), "+f"(c[1]), "+f"(c[2]), "+f"(c[3]) \
        : "r"(a[0]), "r"(a[1]), "r"(a[2]), "r"(a[3]), "r"(b[0]), "r"(b[1]))

// ---------------- init + one-hot table transpose (launch #0) ----------------
__global__ void k_init_woh(const float* __restrict__ w_ih) {
    int idx = blockIdx.x * 256 + threadIdx.x;
    if (idx < 2 * BB * RNN) ((float*)g_hbuf)[idx] = 0.f;
    if (idx < NBLK) g_flag[idx] = 0u;
    if (idx < NC * G3) {
        int g = idx % G3, c = idx / G3;
        g_wohT[(size_t)c * G3 + g] = __ldg(&w_ih[(size_t)g * DIN + c]);
    }
}

// ---------------- mel upsample: one block per (b,f)  (launch #1) ----------------
__global__ void k_upsample(const float* __restrict__ mels,
                           const float* __restrict__ k0,
                           const float* __restrict__ k1,
                           const float* __restrict__ k2) {
    int bf = blockIdx.x;
    int b = bf / FEAT, f = bf % FEAT;
    __shared__ float s0[16], s1[80], s2[400], c0[11], c1[11], c2[23];
    int tid = threadIdx.x;
    if (tid < 16) s0[tid] = mels[((size_t)b * FEAT + f) * 16 + tid];
    if (tid < 11) c0[tid] = k0[tid];
    if (tid < 11) c1[tid] = k1[tid];
    if (tid < 23) c2[tid] = k2[tid];
    __syncthreads();
    if (tid < 80) {
        float a = 0.f;
        #pragma unroll
        for (int u = 0; u < 11; u++) {
            int p = tid + u - 5;
            if (p >= 0 && p < 80) a += c0[u] * s0[p / 5];
        }
        s1[tid] = a;
    }
    __syncthreads();
    if (tid < 400) {
        float a = 0.f;
        #pragma unroll
        for (int u = 0; u < 11; u++) {
            int p = tid + u - 5;
            if (p >= 0 && p < 400) a += c1[u] * s1[p / 5];
        }
        s2[tid] = a;
    }
    __syncthreads();
    for (int i = tid; i < TT; i += blockDim.x) {
        int p = i + 550;
        float a = 0.f;
        #pragma unroll
        for (int u = 0; u < 23; u++) a += c2[u] * s2[(p + u - 11) / 11];
        g_melsup[((size_t)b * TT + i) * FEAT + f] = a;
    }
}

// ---------------- x_proj precompute: one block per 2 timesteps  (launch #2) ----------------
__global__ void __launch_bounds__(256) k_xproj(const int* __restrict__ x,
                                               const float* __restrict__ w_ih,
                                               const float* __restrict__ b_ih) {
    int t0 = blockIdx.x * 2;
    int tid = threadIdx.x;
    __shared__ float mel_s[2][BB][FEAT];
    __shared__ int   cls_s[2][BB];
    for (int i = tid; i < 2 * BB * FEAT; i += 256) {
        int tt = i / (BB * FEAT), rem = i % (BB * FEAT);
        int b = rem / FEAT, f = rem % FEAT;
        mel_s[tt][b][f] = g_melsup[((size_t)b * TT + t0 + tt) * FEAT + f];
    }
    if (tid < 32) cls_s[tid >> 4][tid & 15] = x[(size_t)(tid & 15) * TT + t0 + (tid >> 4)];
    __syncthreads();

    for (int r = tid; r < G3; r += 256) {
        float acc0[BB], acc1[BB];
        float bi = b_ih[r];
        #pragma unroll
        for (int b = 0; b < BB; b++) {
            acc0[b] = bi + g_wohT[(size_t)cls_s[0][b] * G3 + r];
            acc1[b] = bi + g_wohT[(size_t)cls_s[1][b] * G3 + r];
        }
        const float* wrow = &w_ih[(size_t)r * DIN + NC];
        #pragma unroll 4
        for (int fq = 0; fq < FEAT / 4; fq++) {
            float4 w4 = __ldg((const float4*)wrow + fq);
            #pragma unroll
            for (int b = 0; b < BB; b++) {
                float4 m0 = *(const float4*)&mel_s[0][b][4 * fq];
                float4 m1 = *(const float4*)&mel_s[1][b][4 * fq];
                acc0[b] += w4.x * m0.x + w4.y * m0.y + w4.z * m0.z + w4.w * m0.w;
                acc1[b] += w4.x * m1.x + w4.y * m1.y + w4.z * m1.z + w4.w * m1.w;
            }
        }
        float* dst0 = &g_xproj[((size_t)t0 * G3 + r) * BB];
        float* dst1 = &g_xproj[((size_t)(t0 + 1) * G3 + r) * BB];
        #pragma unroll
        for (int q = 0; q < 4; q++) {
            *(float4*)&dst0[4 * q] = make_float4(acc0[4*q], acc0[4*q+1], acc0[4*q+2], acc0[4*q+3]);
            *(float4*)&dst1[4 * q] = make_float4(acc1[4*q], acc1[4*q+1], acc1[4*q+2], acc1[4*q+3]);
        }
    }
}

// ---------------- persistent GRU kernel (launch #3 -> profiled slot) ----------------
// 128 blocks x 256 thr; block owns 4 hidden units (12 gate-rows = 2 MMA n-tiles).
// Y[16b x 12rows] = h(16x512) . W_hh^T via m16n8k8 tf32 3-term split.
// Flag-array grid barrier: st.release flag[bk]; warp0 vector-polls all 128 flags.
__global__ void __launch_bounds__(256, 1) k_gru(const float* __restrict__ w_hh,
                                                const float* __restrict__ b_hh) {
    const int bk = blockIdx.x;
    const int j0 = bk * 4;
    const int tid = threadIdx.x;
    const int wi = tid >> 5, lane = tid & 31;
    const int gid = lane >> 2, tig = lane & 3;
    const int ks0 = wi * 64;                 // this warp's K slice

    __shared__ float Hs[16][516];            // h fp32, stride 516 (conflict-free frags)
    __shared__ float part[8][16][18];        // per-warp partial Y [warp][batch][row]
    __shared__ float xp_s[12][16];
    __shared__ float bhh_s[12];

    // register-resident W fragments (tf32 hi/lo); rows n>=12 zero-padded
    unsigned wbh[2][8][2], wbl[2][8][2];
    #pragma unroll
    for (int nt = 0; nt < 2; nt++) {
        int n = nt * 8 + gid;                // gate-row lr = g*4+u
        bool val = (n < 12);
        size_t row = (size_t)((n >> 2) * RNN + j0 + (n & 3));
        #pragma unroll
        for (int k8 = 0; k8 < 8; k8++) {
            #pragma unroll
            for (int c = 0; c < 2; c++) {
                float wv = val ? w_hh[row * RNN + ks0 + k8 * 8 + c * 4 + tig] : 0.f;
                unsigned hi, lo; split_tf32(wv, hi, lo);
                wbh[nt][k8][c] = hi; wbl[nt][k8][c] = lo;
            }
        }
    }
    if (tid < 12) bhh_s[tid] = b_hh[(tid >> 2) * RNN + j0 + (tid & 3)];

    // xp prefetch state: threads 64..255 cover 12 rows x 16 batches
    int pt = tid - 64;
    int plr = pt >> 4, pb = pt & 15;
    int prow = (plr >> 2) * RNN + j0 + (plr & 3);
    float xp_r = 0.f;
    if (tid >= 64) xp_r = g_xproj[(size_t)prow * BB + pb];   // t=0

    int cur = 0;
    for (int t = 0; t < TT; t++) {
        if (tid >= 64) xp_s[plr][pb] = xp_r;
        {                                     // stage h (L1-bypass, padded rows)
            const float4* src = (const float4*)g_hbuf[cur];
            #pragma unroll
            for (int i = 0; i < 8; i++) {
                int idx = tid + 256 * i;
                float4 v = __ldcg(src + idx);
                *(float4*)&Hs[idx >> 7][4 * (idx & 127)] = v;
            }
        }
        __syncthreads();

        float c0[4] = {0.f, 0.f, 0.f, 0.f}, c1[4] = {0.f, 0.f, 0.f, 0.f};
        #pragma unroll
        for (int k8 = 0; k8 < 8; k8++) {
            int kc = ks0 + k8 * 8 + tig;
            float h0 = Hs[gid][kc],     h1 = Hs[gid + 8][kc];
            float h2 = Hs[gid][kc + 4], h3 = Hs[gid + 8][kc + 4];
            unsigned ah[4], al[4];
            split_tf32(h0, ah[0], al[0]); split_tf32(h1, ah[1], al[1]);
            split_tf32(h2, ah[2], al[2]); split_tf32(h3, ah[3], al[3]);
            MMA_TF32(c0, ah, wbh[0][k8]);
            MMA_TF32(c0, al, wbh[0][k8]);
            MMA_TF32(c0, ah, wbl[0][k8]);
            MMA_TF32(c1, ah, wbh[1][k8]);
            MMA_TF32(c1, al, wbh[1][k8]);
            MMA_TF32(c1, ah, wbl[1][k8]);
        }
        // c frag: {(gid,2tig),(gid,2tig+1),(gid+8,2tig),(gid+8,2tig+1)}, m=batch, n=row
        *(float2*)&part[wi][gid][2 * tig]         = make_float2(c0[0], c0[1]);
        *(float2*)&part[wi][gid + 8][2 * tig]     = make_float2(c0[2], c0[3]);
        *(float2*)&part[wi][gid][8 + 2 * tig]     = make_float2(c1[0], c1[1]);
        *(float2*)&part[wi][gid + 8][8 + 2 * tig] = make_float2(c1[2], c1[3]);
        __syncthreads();

        int nxt = cur ^ 1;
        if (tid < 64) {                       // fused reduce + gates: 4 units x 16 b
            int u = tid >> 4, b = tid & 15;
            float yr = bhh_s[u], yz = bhh_s[4 + u], yn = bhh_s[8 + u];
            #pragma unroll
            for (int w = 0; w < 8; w++) {
                yr += part[w][b][u];
                yz += part[w][b][4 + u];
                yn += part[w][b][8 + u];
            }
            float r = sigm(xp_s[u][b] + yr);
            float z = sigm(xp_s[4 + u][b] + yz);
            float n = ftanh(xp_s[8 + u][b] + r * yn);
            float hv = (1.f - z) * n + z * Hs[b][j0 + u];
            int j = j0 + u;
            __stcg(&g_hbuf[nxt][b * RNN + j], hv);
            g_hs[((size_t)b * TT + t) * RNN + j] = hv;

            // arrival: epilogue warps sync, tid0 publishes the flag
            asm volatile("bar.sync 1, 64;" ::: "memory");
            if (tid == 0)
                asm volatile("st.release.gpu.global.u32 [%0], %1;"
                             :: "l"(g_flag + bk), "r"((unsigned)(t + 1)) : "memory");
            if (wi == 0) {                    // warp 0: vector-poll all 128 flags
                unsigned tgt = (unsigned)(t + 1);
                bool ok;
                do {
                    uint4 v;
                    asm volatile("ld.relaxed.gpu.global.v4.u32 {%0,%1,%2,%3}, [%4];"
                                 : "=r"(v.x), "=r"(v.y), "=r"(v.z), "=r"(v.w)
                                 : "l"((const uint4*)g_flag + lane) : "memory");
                    ok = (v.x >= tgt) & (v.y >= tgt) & (v.z >= tgt) & (v.w >= tgt);
                } while (!__all_sync(0xffffffffu, ok));
                asm volatile("fence.acq_rel.gpu;" ::: "memory");
            }
        } else if (t + 1 < TT) {              // prefetch next xp in parallel
            xp_r = g_xproj[((size_t)(t + 1) * G3 + prow) * BB + pb];
        }
        __syncthreads();
        cur = nxt;
    }
}

// ---------------- 3xTF32 tensor-core GEMM (unchanged, validated) ----------------
template<int ACT>
__global__ void __launch_bounds__(256) k_gemm_tc(const float* __restrict__ A,
                                                 const float* __restrict__ W,
                                                 const float* __restrict__ bias,
                                                 float* __restrict__ C) {
    __shared__ unsigned Ash[64][36], Asl[64][36];
    __shared__ unsigned Bsh[64][36], Bsl[64][36];
    const int m0 = blockIdx.x * 64, n0 = blockIdx.y * 64;
    const int tid = threadIdx.x;
    const int lane = tid & 31, wrp = tid >> 5;
    const int wm = wrp >> 2, wn = wrp & 3;
    const int gid = lane >> 2, tig = lane & 3;

    float c[2][2][4];
    #pragma unroll
    for (int i = 0; i < 2; i++)
        #pragma unroll
        for (int j = 0; j < 2; j++)
            #pragma unroll
            for (int q = 0; q < 4; q++) c[i][j][q] = 0.f;

    for (int kc = 0; kc < 512; kc += 32) {
        __syncthreads();
        #pragma unroll
        for (int i = 0; i < 2; i++) {
            int p = tid + 256 * i;
            int m = p >> 3, kq = p & 7;
            float4 av = *(const float4*)&A[(size_t)(m0 + m) * 512 + kc + 4 * kq];
            float4 bv = *(const float4*)&W[(size_t)(n0 + m) * 512 + kc + 4 * kq];
            unsigned h0,l0,h1,l1,h2,l2,h3,l3;
            split_tf32(av.x, h0, l0); split_tf32(av.y, h1, l1);
            split_tf32(av.z, h2, l2); split_tf32(av.w, h3, l3);
            *(uint4*)&Ash[m][4 * kq] = make_uint4(h0, h1, h2, h3);
            *(uint4*)&Asl[m][4 * kq] = make_uint4(l0, l1, l2, l3);
            split_tf32(bv.x, h0, l0); split_tf32(bv.y, h1, l1);
            split_tf32(bv.z, h2, l2); split_tf32(bv.w, h3, l3);
            *(uint4*)&Bsh[m][4 * kq] = make_uint4(h0, h1, h2, h3);
            *(uint4*)&Bsl[m][4 * kq] = make_uint4(l0, l1, l2, l3);
        }
        __syncthreads();
        #pragma unroll
        for (int k8 = 0; k8 < 32; k8 += 8) {
            unsigned ah[2][4], al[2][4], bh2[2][2], bl2[2][2];
            #pragma unroll
            for (int mt = 0; mt < 2; mt++) {
                int m = wm * 32 + mt * 16 + gid;
                ah[mt][0] = Ash[m][k8 + tig];     ah[mt][1] = Ash[m + 8][k8 + tig];
                ah[mt][2] = Ash[m][k8 + 4 + tig]; ah[mt][3] = Ash[m + 8][k8 + 4 + tig];
                al[mt][0] = Asl[m][k8 + tig];     al[mt][1] = Asl[m + 8][k8 + tig];
                al[mt][2] = Asl[m][k8 + 4 + tig]; al[mt][3] = Asl[m + 8][k8 + 4 + tig];
            }
            #pragma unroll
            for (int nt = 0; nt < 2; nt++) {
                int n = wn * 16 + nt * 8 + gid;
                bh2[nt][0] = Bsh[n][k8 + tig]; bh2[nt][1] = Bsh[n][k8 + 4 + tig];
                bl2[nt][0] = Bsl[n][k8 + tig]; bl2[nt][1] = Bsl[n][k8 + 4 + tig];
            }
            #pragma unroll
            for (int mt = 0; mt < 2; mt++)
                #pragma unroll
                for (int nt = 0; nt < 2; nt++) {
                    MMA_TF32(c[mt][nt], ah[mt], bh2[nt]);
                    MMA_TF32(c[mt][nt], ah[mt], bl2[nt]);
                    MMA_TF32(c[mt][nt], al[mt], bh2[nt]);
                }
        }
    }

    #pragma unroll
    for (int mt = 0; mt < 2; mt++) {
        int m = m0 + wm * 32 + mt * 16 + gid;
        #pragma unroll
        for (int nt = 0; nt < 2; nt++) {
            int n = n0 + wn * 16 + nt * 8 + 2 * tig;
            float b0v = __ldg(&bias[n]), b1v = __ldg(&bias[n + 1]);
            float v0 = c[mt][nt][0] + b0v, v1 = c[mt][nt][1] + b1v;
            float v2 = c[mt][nt][2] + b0v, v3 = c[mt][nt][3] + b1v;
            if (ACT) {
                v0 = fmaxf(v0, 0.f); v1 = fmaxf(v1, 0.f);
                v2 = fmaxf(v2, 0.f); v3 = fmaxf(v3, 0.f);
            }
            *(float2*)&C[(size_t)m * 512 + n]       = make_float2(v0, v1);
            *(float2*)&C[(size_t)(m + 8) * 512 + n] = make_float2(v2, v3);
        }
    }
}

// ---------------- launch ----------------
extern "C" void kernel_launch(void* const* d_in, const int* in_sizes, int n_in,
                              void* d_out, int out_size) {
    const int*   x     = (const int*)  d_in[0];
    const float* mels  = (const float*)d_in[1];
    const float* up_k0 = (const float*)d_in[2];
    const float* up_k1 = (const float*)d_in[3];
    const float* up_k2 = (const float*)d_in[4];
    const float* w_ih  = (const float*)d_in[5];
    const float* w_hh  = (const float*)d_in[6];
    const float* b_ih  = (const float*)d_in[7];
    const float* b_hh  = (const float*)d_in[8];
    const float* fc1_w = (const float*)d_in[9];
    const float* fc1_b = (const float*)d_in[10];
    const float* fc2_w = (const float*)d_in[11];
    const float* fc2_b = (const float*)d_in[12];
    float* out = (float*)d_out;

    float *d_hs, *d_h1;
    cudaGetSymbolAddress((void**)&d_hs, g_hs);
    cudaGetSymbolAddress((void**)&d_h1, g_h1);

    k_init_woh<<<(NC * G3 + 255) / 256, 256>>>(w_ih);           // 0
    k_upsample<<<BB * FEAT, 512>>>(mels, up_k0, up_k1, up_k2);  // 1
    k_xproj<<<TT / 2, 256>>>(x, w_ih, b_ih);                    // 2
    k_gru<<<NBLK, 256>>>(w_hh, b_hh);                           // 3 <- profiled slot

    dim3 gg(BB * TT / 64, 512 / 64);
    k_gemm_tc<1><<<gg, 256>>>(d_hs, fc1_w, fc1_b, d_h1);        // 4
    k_gemm_tc<0><<<gg, 256>>>(d_h1, fc2_w, fc2_b, out);         // 5
}

// round 16
// speedup vs baseline: 3.0253x; 3.0253x over previous
#include <cuda_runtime.h>
#include <math.h>

#define BB    16
#define TT    3300
#define FEAT  80
#define NC    512
#define RNN   512
#define G3    1536
#define DIN   592
#define NBLK  128   // persistent GRU blocks (256 threads each)

// ---------------- device scratch (no allocation allowed) ----------------
__device__ float    g_melsup[(size_t)BB * TT * FEAT];     // [b][t][f]
__device__ float    g_wohT[(size_t)NC * G3];              // [class][gate-row]
__device__ float    g_xproj[(size_t)TT * G3 * BB];        // [t][row][b] (includes b_ih)
__device__ float    g_hs[(size_t)BB * TT * RNN];          // GRU outputs
__device__ float    g_h1[(size_t)BB * TT * RNN];          // fc1 output
__device__ float    g_hbuf[2][BB * RNN];                  // ping-pong hidden state
__device__ unsigned g_cnt;                                // barrier counter

__device__ __forceinline__ float sigm(float x) { return 1.f / (1.f + __expf(-x)); }
__device__ __forceinline__ float ftanh(float x) {
    x = fminf(fmaxf(x, -15.f), 15.f);
    float e = __expf(-2.f * x);
    return __fdividef(1.f - e, 1.f + e);
}

// tf32 hi/lo split + m16n8k8 MMA
__device__ __forceinline__ void split_tf32(float v, unsigned &hi, unsigned &lo) {
    unsigned h;
    asm("cvt.rna.tf32.f32 %0, %1;" : "=r"(h) : "f"(v));
    float l = v - __uint_as_float(h);
    asm("cvt.rna.tf32.f32 %0, %1;" : "=r"(lo) : "f"(l));
    hi = h;
}

#define MMA_TF32(c, a, b) \
    asm volatile("mma.sync.aligned.m16n8k8.row.col.f32.tf32.tf32.f32 " \
        "{%0,%1,%2,%3}, {%4,%5,%6,%7}, {%8,%9}, {%0,%1,%2,%3};" \
        : "+f"(c[0]), "+f"(c[1]), "+f"(c[2]), "+f"(c[3]) \
        : "r"(a[0]), "r"(a[1]), "r"(a[2]), "r"(a[3]), "r"(b[0]), "r"(b[1]))

// ---------------- init + one-hot table transpose (launch #0) ----------------
__global__ void k_init_woh(const float* __restrict__ w_ih) {
    int idx = blockIdx.x * 256 + threadIdx.x;
    if (idx < 2 * BB * RNN) ((float*)g_hbuf)[idx] = 0.f;
    if (idx == 0) g_cnt = 0u;
    if (idx < NC * G3) {
        int g = idx % G3, c = idx / G3;
        g_wohT[(size_t)c * G3 + g] = __ldg(&w_ih[(size_t)g * DIN + c]);
    }
}

// ---------------- mel upsample: one block per (b,f)  (launch #1) ----------------
__global__ void k_upsample(const float* __restrict__ mels,
                           const float* __restrict__ k0,
                           const float* __restrict__ k1,
                           const float* __restrict__ k2) {
    int bf = blockIdx.x;
    int b = bf / FEAT, f = bf % FEAT;
    __shared__ float s0[16], s1[80], s2[400], c0[11], c1[11], c2[23];
    int tid = threadIdx.x;
    if (tid < 16) s0[tid] = mels[((size_t)b * FEAT + f) * 16 + tid];
    if (tid < 11) c0[tid] = k0[tid];
    if (tid < 11) c1[tid] = k1[tid];
    if (tid < 23) c2[tid] = k2[tid];
    __syncthreads();
    if (tid < 80) {
        float a = 0.f;
        #pragma unroll
        for (int u = 0; u < 11; u++) {
            int p = tid + u - 5;
            if (p >= 0 && p < 80) a += c0[u] * s0[p / 5];
        }
        s1[tid] = a;
    }
    __syncthreads();
    if (tid < 400) {
        float a = 0.f;
        #pragma unroll
        for (int u = 0; u < 11; u++) {
            int p = tid + u - 5;
            if (p >= 0 && p < 400) a += c1[u] * s1[p / 5];
        }
        s2[tid] = a;
    }
    __syncthreads();
    for (int i = tid; i < TT; i += blockDim.x) {
        int p = i + 550;
        float a = 0.f;
        #pragma unroll
        for (int u = 0; u < 23; u++) a += c2[u] * s2[(p + u - 11) / 11];
        g_melsup[((size_t)b * TT + i) * FEAT + f] = a;
    }
}

// ---------------- x_proj precompute: one block per 2 timesteps  (launch #2) ----------------
__global__ void __launch_bounds__(256) k_xproj(const int* __restrict__ x,
                                               const float* __restrict__ w_ih,
                                               const float* __restrict__ b_ih) {
    int t0 = blockIdx.x * 2;
    int tid = threadIdx.x;
    __shared__ float mel_s[2][BB][FEAT];
    __shared__ int   cls_s[2][BB];
    for (int i = tid; i < 2 * BB * FEAT; i += 256) {
        int tt = i / (BB * FEAT), rem = i % (BB * FEAT);
        int b = rem / FEAT, f = rem % FEAT;
        mel_s[tt][b][f] = g_melsup[((size_t)b * TT + t0 + tt) * FEAT + f];
    }
    if (tid < 32) cls_s[tid >> 4][tid & 15] = x[(size_t)(tid & 15) * TT + t0 + (tid >> 4)];
    __syncthreads();

    for (int r = tid; r < G3; r += 256) {
        float acc0[BB], acc1[BB];
        float bi = b_ih[r];
        #pragma unroll
        for (int b = 0; b < BB; b++) {
            acc0[b] = bi + g_wohT[(size_t)cls_s[0][b] * G3 + r];
            acc1[b] = bi + g_wohT[(size_t)cls_s[1][b] * G3 + r];
        }
        const float* wrow = &w_ih[(size_t)r * DIN + NC];
        #pragma unroll 4
        for (int fq = 0; fq < FEAT / 4; fq++) {
            float4 w4 = __ldg((const float4*)wrow + fq);
            #pragma unroll
            for (int b = 0; b < BB; b++) {
                float4 m0 = *(const float4*)&mel_s[0][b][4 * fq];
                float4 m1 = *(const float4*)&mel_s[1][b][4 * fq];
                acc0[b] += w4.x * m0.x + w4.y * m0.y + w4.z * m0.z + w4.w * m0.w;
                acc1[b] += w4.x * m1.x + w4.y * m1.y + w4.z * m1.z + w4.w * m1.w;
            }
        }
        float* dst0 = &g_xproj[((size_t)t0 * G3 + r) * BB];
        float* dst1 = &g_xproj[((size_t)(t0 + 1) * G3 + r) * BB];
        #pragma unroll
        for (int q = 0; q < 4; q++) {
            *(float4*)&dst0[4 * q] = make_float4(acc0[4*q], acc0[4*q+1], acc0[4*q+2], acc0[4*q+3]);
            *(float4*)&dst1[4 * q] = make_float4(acc1[4*q], acc1[4*q+1], acc1[4*q+2], acc1[4*q+3]);
        }
    }
}

// ---------------- persistent GRU kernel (launch #3 -> profiled slot) ----------------
// R10-proven core: 128 blocks x 256 thr; block owns 4 hidden units (12 gate-rows).
// Y[16b x 12rows] = h(16x512) . W_hh^T via m16n8k8 tf32 3-term split.
// Barrier: single counter, tid0 red.release arrive (early, after 64-thr bar) +
// tid0 acquire poll. ONE poller lane per block on ONE line (proven shape).
__global__ void __launch_bounds__(256, 1) k_gru(const float* __restrict__ w_hh,
                                                const float* __restrict__ b_hh) {
    const int bk = blockIdx.x;
    const int j0 = bk * 4;
    const int tid = threadIdx.x;
    const int wi = tid >> 5, lane = tid & 31;
    const int gid = lane >> 2, tig = lane & 3;
    const int ks0 = wi * 64;                 // this warp's K slice

    __shared__ float Hs[16][516];            // h fp32, stride 516 (conflict-free frags)
    __shared__ float part[8][16][18];        // per-warp partial Y [warp][batch][row]
    __shared__ float xp_s[12][16];
    __shared__ float bhh_s[12];

    // register-resident W fragments (tf32 hi/lo); rows n>=12 zero-padded
    unsigned wbh[2][8][2], wbl[2][8][2];
    #pragma unroll
    for (int nt = 0; nt < 2; nt++) {
        int n = nt * 8 + gid;                // gate-row lr = g*4+u
        bool val = (n < 12);
        size_t row = (size_t)((n >> 2) * RNN + j0 + (n & 3));
        #pragma unroll
        for (int k8 = 0; k8 < 8; k8++) {
            #pragma unroll
            for (int c = 0; c < 2; c++) {
                float wv = val ? w_hh[row * RNN + ks0 + k8 * 8 + c * 4 + tig] : 0.f;
                unsigned hi, lo; split_tf32(wv, hi, lo);
                wbh[nt][k8][c] = hi; wbl[nt][k8][c] = lo;
            }
        }
    }
    if (tid < 12) bhh_s[tid] = b_hh[(tid >> 2) * RNN + j0 + (tid & 3)];

    // xp prefetch state: threads 64..255 cover 12 rows x 16 batches
    int pt = tid - 64;
    int plr = pt >> 4, pb = pt & 15;
    int prow = (plr >> 2) * RNN + j0 + (plr & 3);
    float xp_r = 0.f;
    if (tid >= 64) xp_r = g_xproj[(size_t)prow * BB + pb];   // t=0

    unsigned* cnt_p = &g_cnt;
    int cur = 0;
    for (int t = 0; t < TT; t++) {
        if (tid >= 64) xp_s[plr][pb] = xp_r;
        {                                     // stage h (L1-bypass, padded rows)
            const float4* src = (const float4*)g_hbuf[cur];
            #pragma unroll
            for (int i = 0; i < 8; i++) {
                int idx = tid + 256 * i;
                float4 v = __ldcg(src + idx);
                *(float4*)&Hs[idx >> 7][4 * (idx & 127)] = v;
            }
        }
        __syncthreads();

        float c0[4] = {0.f, 0.f, 0.f, 0.f}, c1[4] = {0.f, 0.f, 0.f, 0.f};
        #pragma unroll
        for (int k8 = 0; k8 < 8; k8++) {
            int kc = ks0 + k8 * 8 + tig;
            float h0 = Hs[gid][kc],     h1 = Hs[gid + 8][kc];
            float h2 = Hs[gid][kc + 4], h3 = Hs[gid + 8][kc + 4];
            unsigned ah[4], al[4];
            split_tf32(h0, ah[0], al[0]); split_tf32(h1, ah[1], al[1]);
            split_tf32(h2, ah[2], al[2]); split_tf32(h3, ah[3], al[3]);
            MMA_TF32(c0, ah, wbh[0][k8]);
            MMA_TF32(c0, al, wbh[0][k8]);
            MMA_TF32(c0, ah, wbl[0][k8]);
            MMA_TF32(c1, ah, wbh[1][k8]);
            MMA_TF32(c1, al, wbh[1][k8]);
            MMA_TF32(c1, ah, wbl[1][k8]);
        }
        // c frag: {(gid,2tig),(gid,2tig+1),(gid+8,2tig),(gid+8,2tig+1)}, m=batch, n=row
        *(float2*)&part[wi][gid][2 * tig]         = make_float2(c0[0], c0[1]);
        *(float2*)&part[wi][gid + 8][2 * tig]     = make_float2(c0[2], c0[3]);
        *(float2*)&part[wi][gid][8 + 2 * tig]     = make_float2(c1[0], c1[1]);
        *(float2*)&part[wi][gid + 8][8 + 2 * tig] = make_float2(c1[2], c1[3]);
        __syncthreads();

        int nxt = cur ^ 1;
        if (tid < 64) {                       // fused reduce + gates: 4 units x 16 b
            int u = tid >> 4, b = tid & 15;
            float yr = bhh_s[u], yz = bhh_s[4 + u], yn = bhh_s[8 + u];
            #pragma unroll
            for (int w = 0; w < 8; w++) {
                yr += part[w][b][u];
                yz += part[w][b][4 + u];
                yn += part[w][b][8 + u];
            }
            float r = sigm(xp_s[u][b] + yr);
            float z = sigm(xp_s[4 + u][b] + yz);
            float n = ftanh(xp_s[8 + u][b] + r * yn);
            float hv = (1.f - z) * n + z * Hs[b][j0 + u];
            int j = j0 + u;
            __stcg(&g_hbuf[nxt][b * RNN + j], hv);
            g_hs[((size_t)b * TT + t) * RNN + j] = hv;

            // early arrival: epilogue warps sync, tid0 releases the counter
            asm volatile("bar.sync 1, 64;" ::: "memory");
            if (tid == 0)
                asm volatile("red.release.gpu.global.add.u32 [%0], 1;" :: "l"(cnt_p) : "memory");
        } else if (t + 1 < TT) {              // prefetch next xp in parallel
            xp_r = g_xproj[((size_t)(t + 1) * G3 + prow) * BB + pb];
        }
        __syncthreads();
        if (tid == 0) {                       // acquire poll: one lane, one line
            unsigned tgt = (unsigned)(t + 1) * (unsigned)NBLK;
            unsigned v;
            do {
                asm volatile("ld.acquire.gpu.global.u32 %0, [%1];" : "=r"(v) : "l"(cnt_p) : "memory");
            } while (v < tgt);
        }
        __syncthreads();
        cur = nxt;
    }
}

// ---------------- 3xTF32 tensor-core GEMM (unchanged, validated) ----------------
template<int ACT>
__global__ void __launch_bounds__(256) k_gemm_tc(const float* __restrict__ A,
                                                 const float* __restrict__ W,
                                                 const float* __restrict__ bias,
                                                 float* __restrict__ C) {
    __shared__ unsigned Ash[64][36], Asl[64][36];
    __shared__ unsigned Bsh[64][36], Bsl[64][36];
    const int m0 = blockIdx.x * 64, n0 = blockIdx.y * 64;
    const int tid = threadIdx.x;
    const int lane = tid & 31, wrp = tid >> 5;
    const int wm = wrp >> 2, wn = wrp & 3;
    const int gid = lane >> 2, tig = lane & 3;

    float c[2][2][4];
    #pragma unroll
    for (int i = 0; i < 2; i++)
        #pragma unroll
        for (int j = 0; j < 2; j++)
            #pragma unroll
            for (int q = 0; q < 4; q++) c[i][j][q] = 0.f;

    for (int kc = 0; kc < 512; kc += 32) {
        __syncthreads();
        #pragma unroll
        for (int i = 0; i < 2; i++) {
            int p = tid + 256 * i;
            int m = p >> 3, kq = p & 7;
            float4 av = *(const float4*)&A[(size_t)(m0 + m) * 512 + kc + 4 * kq];
            float4 bv = *(const float4*)&W[(size_t)(n0 + m) * 512 + kc + 4 * kq];
            unsigned h0,l0,h1,l1,h2,l2,h3,l3;
            split_tf32(av.x, h0, l0); split_tf32(av.y, h1, l1);
            split_tf32(av.z, h2, l2); split_tf32(av.w, h3, l3);
            *(uint4*)&Ash[m][4 * kq] = make_uint4(h0, h1, h2, h3);
            *(uint4*)&Asl[m][4 * kq] = make_uint4(l0, l1, l2, l3);
            split_tf32(bv.x, h0, l0); split_tf32(bv.y, h1, l1);
            split_tf32(bv.z, h2, l2); split_tf32(bv.w, h3, l3);
            *(uint4*)&Bsh[m][4 * kq] = make_uint4(h0, h1, h2, h3);
            *(uint4*)&Bsl[m][4 * kq] = make_uint4(l0, l1, l2, l3);
        }
        __syncthreads();
        #pragma unroll
        for (int k8 = 0; k8 < 32; k8 += 8) {
            unsigned ah[2][4], al[2][4], bh2[2][2], bl2[2][2];
            #pragma unroll
            for (int mt = 0; mt < 2; mt++) {
                int m = wm * 32 + mt * 16 + gid;
                ah[mt][0] = Ash[m][k8 + tig];     ah[mt][1] = Ash[m + 8][k8 + tig];
                ah[mt][2] = Ash[m][k8 + 4 + tig]; ah[mt][3] = Ash[m + 8][k8 + 4 + tig];
                al[mt][0] = Asl[m][k8 + tig];     al[mt][1] = Asl[m + 8][k8 + tig];
                al[mt][2] = Asl[m][k8 + 4 + tig]; al[mt][3] = Asl[m + 8][k8 + 4 + tig];
            }
            #pragma unroll
            for (int nt = 0; nt < 2; nt++) {
                int n = wn * 16 + nt * 8 + gid;
                bh2[nt][0] = Bsh[n][k8 + tig]; bh2[nt][1] = Bsh[n][k8 + 4 + tig];
                bl2[nt][0] = Bsl[n][k8 + tig]; bl2[nt][1] = Bsl[n][k8 + 4 + tig];
            }
            #pragma unroll
            for (int mt = 0; mt < 2; mt++)
                #pragma unroll
                for (int nt = 0; nt < 2; nt++) {
                    MMA_TF32(c[mt][nt], ah[mt], bh2[nt]);
                    MMA_TF32(c[mt][nt], ah[mt], bl2[nt]);
                    MMA_TF32(c[mt][nt], al[mt], bh2[nt]);
                }
        }
    }

    #pragma unroll
    for (int mt = 0; mt < 2; mt++) {
        int m = m0 + wm * 32 + mt * 16 + gid;
        #pragma unroll
        for (int nt = 0; nt < 2; nt++) {
            int n = n0 + wn * 16 + nt * 8 + 2 * tig;
            float b0v = __ldg(&bias[n]), b1v = __ldg(&bias[n + 1]);
            float v0 = c[mt][nt][0] + b0v, v1 = c[mt][nt][1] + b1v;
            float v2 = c[mt][nt][2] + b0v, v3 = c[mt][nt][3] + b1v;
            if (ACT) {
                v0 = fmaxf(v0, 0.f); v1 = fmaxf(v1, 0.f);
                v2 = fmaxf(v2, 0.f); v3 = fmaxf(v3, 0.f);
            }
            *(float2*)&C[(size_t)m * 512 + n]       = make_float2(v0, v1);
            *(float2*)&C[(size_t)(m + 8) * 512 + n] = make_float2(v2, v3);
        }
    }
}

// ---------------- launch ----------------
extern "C" void kernel_launch(void* const* d_in, const int* in_sizes, int n_in,
                              void* d_out, int out_size) {
    const int*   x     = (const int*)  d_in[0];
    const float* mels  = (const float*)d_in[1];
    const float* up_k0 = (const float*)d_in[2];
    const float* up_k1 = (const float*)d_in[3];
    const float* up_k2 = (const float*)d_in[4];
    const float* w_ih  = (const float*)d_in[5];
    const float* w_hh  = (const float*)d_in[6];
    const float* b_ih  = (const float*)d_in[7];
    const float* b_hh  = (const float*)d_in[8];
    const float* fc1_w = (const float*)d_in[9];
    const float* fc1_b = (const float*)d_in[10];
    const float* fc2_w = (const float*)d_in[11];
    const float* fc2_b = (const float*)d_in[12];
    float* out = (float*)d_out;

    float *d_hs, *d_h1;
    cudaGetSymbolAddress((void**)&d_hs, g_hs);
    cudaGetSymbolAddress((void**)&d_h1, g_h1);

    k_init_woh<<<(NC * G3 + 255) / 256, 256>>>(w_ih);           // 0
    k_upsample<<<BB * FEAT, 512>>>(mels, up_k0, up_k1, up_k2);  // 1
    k_xproj<<<TT / 2, 256>>>(x, w_ih, b_ih);                    // 2
    k_gru<<<NBLK, 256>>>(w_hh, b_hh);                           // 3 <- profiled slot

    dim3 gg(BB * TT / 64, 512 / 64);
    k_gemm_tc<1><<<gg, 256>>>(d_hs, fc1_w, fc1_b, d_h1);        // 4
    k_gemm_tc<0><<<gg, 256>>>(d_h1, fc2_w, fc2_b, out);         // 5
}